// round 9
// baseline (speedup 1.0000x reference)
#include <cuda_runtime.h>
#include <cstdint>

// ============================================================
// RSNN: out = LIF16(x @ W^T + b)/16,  M=32768, N=512, K=512 fp32
// Bit-exact fp32 GEMM (k-sequential FMA == reference rounding) on
// the FFMA2 pipe. Pre-passes build XT[k][m] and dup'd WD[k][2n] so
// the GEMM uses cp.async (no reg staging) at 2 CTAs/SM occupancy.
// Loader fills ALL 16 k-rows of both stages (A: 2 units/thread,
// B: 4 units/thread = 24576 B/stage exactly).
// ============================================================

typedef unsigned int u32;
typedef unsigned long long ull;

#define KD 512
#define ND 512
#define MAXM 32768

// static scratch (no allocation allowed)
__device__ float g_xt[(size_t)KD * MAXM];       // 64 MB  XT[k][m]
__device__ float g_wd[(size_t)KD * 2 * ND];     // 2 MB   WD[k][2n] (dup pairs)

#define SWZ(off) ((off) ^ (((off) >> 3) & 0x70))

__device__ __forceinline__ u32 smem_u32(const void* p) {
    u32 a;
    asm("{ .reg .u64 t; cvta.to.shared.u64 t, %1; cvt.u32.u64 %0, t; }" : "=r"(a) : "l"(p));
    return a;
}
__device__ __forceinline__ void cpa16(u32 dst, const void* src) {
    asm volatile("cp.async.cg.shared.global [%0], [%1], 16;" :: "r"(dst), "l"(src));
}
#define CP_COMMIT()  asm volatile("cp.async.commit_group;" ::: "memory")
#define CP_WAIT1()   asm volatile("cp.async.wait_group 1;" ::: "memory")
#define CP_WAIT0()   asm volatile("cp.async.wait_group 0;" ::: "memory")

__device__ __forceinline__ void ffma2(ull& d, ull a, ull b) {
    asm("fma.rn.f32x2 %0, %1, %2, %3;" : "=l"(d) : "l"(a), "l"(b), "l"(d));
}
__device__ __forceinline__ void unpack2(ull v, float& lo, float& hi) {
    u32 l, h;
    asm("mov.b64 {%0, %1}, %2;" : "=r"(l), "=r"(h) : "l"(v));
    lo = __uint_as_float(l);
    hi = __uint_as_float(h);
}

// LIF: identical fp ops to reference per step
__device__ __forceinline__ float lif16(float cur) {
    float v = 0.0f, cnt = 0.0f;
#pragma unroll
    for (int t = 0; t < 16; t++) {
        v = fmaf(cur - v, 0.5f, v);
        if (v >= 1.0f) { cnt += 1.0f; v = 0.0f; }
    }
    return cnt * 0.0625f;
}

// ---------------- pre-pass 1: XT[k][m] = X[m][k] ----------------
__global__ void transpose_x(const float* __restrict__ X, int M, int K) {
    __shared__ float t[32][33];
    const int kb = blockIdx.x * 32, mb = blockIdx.y * 32;
    const int tx = threadIdx.x, ty = threadIdx.y;   // 32 x 8
#pragma unroll
    for (int i = 0; i < 4; i++)
        t[ty + 8 * i][tx] = X[(size_t)(mb + ty + 8 * i) * K + kb + tx];
    __syncthreads();
#pragma unroll
    for (int i = 0; i < 4; i++)
        g_xt[(size_t)(kb + ty + 8 * i) * M + mb + tx] = t[tx][ty + 8 * i];
}

// ---------------- pre-pass 2: WD[k][2n..2n+1] = W[n][k] ----------------
__global__ void dup_w(const float* __restrict__ W, int N, int K) {
    int idx = blockIdx.x * 256 + threadIdx.x;     // n*K + k
    if (idx >= N * K) return;
    int n = idx / K, k = idx - n * K;
    float v = W[idx];
    float2 p = {v, v};
    *reinterpret_cast<float2*>(&g_wd[(size_t)k * 2 * N + 2 * n]) = p;
}

// ---------------- GEMM + LIF ----------------
#define BM 128
#define BN 128
#define BK 16
#define NST 3
#define A_ST (BK * BM * 4)          // 8192  (A stage: [k][m], rows 512B)
#define B_ST (BK * BN * 2 * 4)      // 16384 (B stage: [k][2n] swizzled, rows 1024B)
#define STAGE (A_ST + B_ST)         // 24576
#define SM_TOTAL (NST * STAGE)      // 73728

__global__ void __launch_bounds__(256, 2)
gemm_lif(const float* __restrict__ bias, float* __restrict__ out, int M) {
    extern __shared__ char smem[];
    const u32 sb = smem_u32(smem);
    const int tid = threadIdx.x;
    const int tx = tid & 15;            // n: 16 x 8 = 128
    const int ty = tid >> 4;            // m: 16 x 8 = 128
    const int n0 = blockIdx.x * BN;     // n fastest -> A tile shared in L2 by 4 CTAs
    const int m0 = blockIdx.y * BM;

    // ---- loader mapping (fills full 24576-B stage: 2 A + 4 B units/thread) ----
    const int ak = tid >> 5, au = tid & 31;      // A rows ak, ak+8 ; 32 units/row
    const float* asrc = g_xt + (size_t)ak * M + m0 + au * 4;
    const u32 adst = ak * 512 + au * 16;
    const int bk = tid >> 6, bu = tid & 63;      // B rows bk,+4,+8,+12 ; 64 units/row
    const float* bsrc = g_wd + (size_t)bk * (2 * ND) + n0 * 2 + bu * 4;
    const u32 bswz = SWZ(bu * 16);

    const int NCHUNK = KD / BK;                  // 32

    // prologue: stages 0,1
#pragma unroll
    for (int c = 0; c < 2; c++) {
        u32 s = sb + c * STAGE;
        size_t kofs = (size_t)c * BK;
        cpa16(s + adst,            asrc + kofs * M);
        cpa16(s + adst + 8 * 512,  asrc + (kofs + 8) * M);
#pragma unroll
        for (int r = 0; r < 4; r++)
            cpa16(s + A_ST + (bk + 4 * r) * 1024 + bswz,
                  bsrc + (kofs + 4 * r) * (2 * ND));
        CP_COMMIT();
    }

    ull acc[4][8];
#pragma unroll
    for (int i = 0; i < 4; i++)
#pragma unroll
        for (int j = 0; j < 8; j++) acc[i][j] = 0ull;

    int stage = 0;
    for (int c = 0; c < NCHUNK; c++) {
        if (c == NCHUNK - 1) CP_WAIT0(); else CP_WAIT1();
        __syncthreads();

        const char* st = smem + stage * STAGE;
#pragma unroll
        for (int k = 0; k < BK; k++) {
            union { float4 v; ull u[2]; } a0, a1, bq;
            a0.v = *reinterpret_cast<const float4*>(st + k * 512 + ty * 32);
            a1.v = *reinterpret_cast<const float4*>(st + k * 512 + ty * 32 + 16);
            ull ap[4] = { a0.u[0], a0.u[1], a1.u[0], a1.u[1] };

            const char* bbase = st + A_ST + k * 1024;
#pragma unroll
            for (int h = 0; h < 2; h++) {          // two j-halves keep live regs low
                ull bp[4];
                u32 o0 = tx * 64 + h * 32;
                bq.v = *reinterpret_cast<const float4*>(bbase + SWZ(o0));
                bp[0] = bq.u[0]; bp[1] = bq.u[1];
                bq.v = *reinterpret_cast<const float4*>(bbase + SWZ(o0 + 16));
                bp[2] = bq.u[0]; bp[3] = bq.u[1];
#pragma unroll
                for (int i = 0; i < 4; i++)
#pragma unroll
                    for (int j = 0; j < 4; j++)
                        ffma2(acc[i][h * 4 + j], ap[i], bp[j]);
            }
        }

        if (c + 2 < NCHUNK) {
            int cn = c + 2;
            u32 s = sb + ((stage + 2) % NST) * STAGE;
            size_t kofs = (size_t)cn * BK;
            cpa16(s + adst,            asrc + kofs * M);
            cpa16(s + adst + 8 * 512,  asrc + (kofs + 8) * M);
#pragma unroll
            for (int r = 0; r < 4; r++)
                cpa16(s + A_ST + (bk + 4 * r) * 1024 + bswz,
                      bsrc + (kofs + 4 * r) * (2 * ND));
            CP_COMMIT();
        }
        stage = (stage + 1) % NST;
        __syncthreads();
    }

    // ---- epilogue: bias + LIF + store ----
    float4 bq0 = *reinterpret_cast<const float4*>(bias + n0 + tx * 8);
    float4 bq1 = *reinterpret_cast<const float4*>(bias + n0 + tx * 8 + 4);
    const float bv[8] = { bq0.x, bq0.y, bq0.z, bq0.w, bq1.x, bq1.y, bq1.z, bq1.w };

#pragma unroll
    for (int i = 0; i < 4; i++) {
        float lo[8], hi[8];
#pragma unroll
        for (int j = 0; j < 8; j++) unpack2(acc[i][j], lo[j], hi[j]);

        int m_lo = m0 + ty * 8 + 2 * i;
        float* p0 = out + (size_t)m_lo * ND + n0 + tx * 8;
        float* p1 = p0 + ND;

        float4 o;
        o.x = lif16(lo[0] + bv[0]); o.y = lif16(lo[1] + bv[1]);
        o.z = lif16(lo[2] + bv[2]); o.w = lif16(lo[3] + bv[3]);
        *reinterpret_cast<float4*>(p0) = o;
        o.x = lif16(lo[4] + bv[4]); o.y = lif16(lo[5] + bv[5]);
        o.z = lif16(lo[6] + bv[6]); o.w = lif16(lo[7] + bv[7]);
        *reinterpret_cast<float4*>(p0 + 4) = o;
        o.x = lif16(hi[0] + bv[0]); o.y = lif16(hi[1] + bv[1]);
        o.z = lif16(hi[2] + bv[2]); o.w = lif16(hi[3] + bv[3]);
        *reinterpret_cast<float4*>(p1) = o;
        o.x = lif16(hi[4] + bv[4]); o.y = lif16(hi[5] + bv[5]);
        o.z = lif16(hi[6] + bv[6]); o.w = lif16(hi[7] + bv[7]);
        *reinterpret_cast<float4*>(p1 + 4) = o;
    }
}

extern "C" void kernel_launch(void* const* d_in, const int* in_sizes, int n_in,
                              void* d_out, int out_size) {
    const float* x = (const float*)d_in[0];
    const float* W = (const float*)d_in[1];
    const float* b = (const float*)d_in[2];
    float* out = (float*)d_out;

    const int N = in_sizes[2];          // 512
    const int K = in_sizes[1] / N;      // 512
    const int M = in_sizes[0] / K;      // 32768

    dim3 tb(32, 8);
    dim3 tg(K / 32, M / 32);
    transpose_x<<<tg, tb>>>(x, M, K);
    dup_w<<<(N * K + 255) / 256, 256>>>(W, N, K);

    cudaFuncSetAttribute(gemm_lif, cudaFuncAttributeMaxDynamicSharedMemorySize, SM_TOTAL);
    dim3 grid(N / BN, M / BM);
    gemm_lif<<<grid, 256, SM_TOTAL>>>(b, out, M);
}

// round 10
// speedup vs baseline: 1.6399x; 1.6399x over previous
#include <cuda_runtime.h>
#include <cstdint>

// ============================================================
// RSNN: out = LIF16(x @ W^T + b)/16,  M=32768, N=512, K=512 fp32
// Bit-exact fp32 GEMM (k-sequential FMA == reference rounding) on
// the FFMA2 pipe, cp.async 3-stage pipeline, 2 CTAs/SM.
// R10: register-diet (2 src pointers + imm offsets, single barrier
// per chunk) so the 128-reg cap of (256,2) holds without spills.
// ============================================================

typedef unsigned int u32;
typedef unsigned long long ull;

#define KD 512
#define ND 512
#define MAXM 32768

__device__ float g_xt[(size_t)KD * MAXM];       // 64 MB  XT[k][m]
__device__ float g_wd[(size_t)KD * 2 * ND];     // 2 MB   WD[k][2n] (dup pairs)

#define SWZ(off) ((off) ^ (((off) >> 3) & 0x70))

__device__ __forceinline__ u32 smem_u32(const void* p) {
    u32 a;
    asm("{ .reg .u64 t; cvta.to.shared.u64 t, %1; cvt.u32.u64 %0, t; }" : "=r"(a) : "l"(p));
    return a;
}
__device__ __forceinline__ void cpa16(u32 dst, const float* src) {
    asm volatile("cp.async.cg.shared.global [%0], [%1], 16;" :: "r"(dst), "l"(src));
}
#define CP_COMMIT()  asm volatile("cp.async.commit_group;" ::: "memory")
#define CP_WAIT1()   asm volatile("cp.async.wait_group 1;" ::: "memory")
#define CP_WAIT0()   asm volatile("cp.async.wait_group 0;" ::: "memory")

__device__ __forceinline__ void ffma2(ull& d, ull a, ull b) {
    asm("fma.rn.f32x2 %0, %1, %2, %3;" : "=l"(d) : "l"(a), "l"(b), "l"(d));
}
__device__ __forceinline__ void unpack2(ull v, float& lo, float& hi) {
    u32 l, h;
    asm("mov.b64 {%0, %1}, %2;" : "=r"(l), "=r"(h) : "l"(v));
    lo = __uint_as_float(l);
    hi = __uint_as_float(h);
}

// LIF: identical fp ops to reference per step
__device__ __forceinline__ float lif16(float cur) {
    float v = 0.0f, cnt = 0.0f;
#pragma unroll
    for (int t = 0; t < 16; t++) {
        v = fmaf(cur - v, 0.5f, v);
        if (v >= 1.0f) { cnt += 1.0f; v = 0.0f; }
    }
    return cnt * 0.0625f;
}

// ---------------- pre-pass 1: XT[k][m] = X[m][k] ----------------
__global__ void transpose_x(const float* __restrict__ X, int M, int K) {
    __shared__ float t[32][33];
    const int kb = blockIdx.x * 32, mb = blockIdx.y * 32;
    const int tx = threadIdx.x, ty = threadIdx.y;   // 32 x 8
#pragma unroll
    for (int i = 0; i < 4; i++)
        t[ty + 8 * i][tx] = X[(size_t)(mb + ty + 8 * i) * K + kb + tx];
    __syncthreads();
#pragma unroll
    for (int i = 0; i < 4; i++)
        g_xt[(size_t)(kb + ty + 8 * i) * M + mb + tx] = t[tx][ty + 8 * i];
}

// ---------------- pre-pass 2: WD[k][2n..2n+1] = W[n][k] ----------------
__global__ void dup_w(const float* __restrict__ W, int N, int K) {
    int idx = blockIdx.x * 256 + threadIdx.x;     // n*K + k
    if (idx >= N * K) return;
    int n = idx / K, k = idx - n * K;
    float v = W[idx];
    float2 p = {v, v};
    *reinterpret_cast<float2*>(&g_wd[(size_t)k * 2 * N + 2 * n]) = p;
}

// ---------------- GEMM + LIF ----------------
#define BM 128
#define BN 128
#define BK 16
#define NST 3
#define A_ST (BK * BM * 4)          // 8192
#define B_ST (BK * BN * 2 * 4)      // 16384
#define STAGE (A_ST + B_ST)         // 24576
#define SM_TOTAL (NST * STAGE)      // 73728

__global__ void __launch_bounds__(256, 2)
gemm_lif(const float* __restrict__ bias, float* __restrict__ out, int M) {
    extern __shared__ char smem[];
    const u32 sb = smem_u32(smem);
    const int tid = threadIdx.x;
    const int n0 = blockIdx.x * BN;     // n fastest -> A tile shared in L2 by 4 CTAs
    const int m0 = blockIdx.y * BM;

    // loader: A rows (tid>>5), +8 ; B rows (tid>>6), +4, +8, +12
    const u32 adst = (tid >> 5) * 512 + (tid & 31) * 16;
    const u32 bdst = A_ST + (tid >> 6) * 1024 + SWZ((tid & 63) * 16);
    const float* ai = g_xt + (size_t)(tid >> 5) * M + m0 + (tid & 31) * 4;
    const float* bi = g_wd + (size_t)(tid >> 6) * (2 * ND) + n0 * 2 + (tid & 63) * 4;

    const int NCHUNK = KD / BK;                  // 32

    // prologue: stages 0,1
#pragma unroll
    for (int c = 0; c < 2; c++) {
        u32 s = sb + c * STAGE;
        cpa16(s + adst,        ai);
        cpa16(s + adst + 4096, ai + (size_t)8 * M);
        cpa16(s + bdst,         bi);
        cpa16(s + bdst + 4096,  bi + 4 * 2 * ND);
        cpa16(s + bdst + 8192,  bi + 8 * 2 * ND);
        cpa16(s + bdst + 12288, bi + 12 * 2 * ND);
        CP_COMMIT();
        ai += (size_t)BK * M;
        bi += BK * 2 * ND;
    }

    ull acc[4][8];
#pragma unroll
    for (int i = 0; i < 4; i++)
#pragma unroll
        for (int j = 0; j < 8; j++) acc[i][j] = 0ull;

    const int ty = tid >> 4;            // m: 16 x 8 = 128
    const int tx = tid & 15;            // n: 16 x 8 = 128

    for (int c = 0; c < NCHUNK; c++) {
        if (c >= NCHUNK - 2) CP_WAIT0(); else CP_WAIT1();
        __syncthreads();

        // issue chunk c+2 into buffer (c+2)%3 (its last readers synced above)
        if (c + 2 < NCHUNK) {
            u32 s = sb + ((c + 2) % NST) * STAGE;
            cpa16(s + adst,        ai);
            cpa16(s + adst + 4096, ai + (size_t)8 * M);
            cpa16(s + bdst,         bi);
            cpa16(s + bdst + 4096,  bi + 4 * 2 * ND);
            cpa16(s + bdst + 8192,  bi + 8 * 2 * ND);
            cpa16(s + bdst + 12288, bi + 12 * 2 * ND);
            CP_COMMIT();
            ai += (size_t)BK * M;
            bi += BK * 2 * ND;
        }

        const char* st = smem + (c % NST) * STAGE;
#pragma unroll
        for (int k = 0; k < BK; k++) {
            union { float4 v; ull u[2]; } a0, a1, bq;
            a0.v = *reinterpret_cast<const float4*>(st + k * 512 + ty * 32);
            a1.v = *reinterpret_cast<const float4*>(st + k * 512 + ty * 32 + 16);
            ull ap[4] = { a0.u[0], a0.u[1], a1.u[0], a1.u[1] };

            const char* bbase = st + A_ST + k * 1024;
#pragma unroll
            for (int h = 0; h < 2; h++) {
                ull bp[4];
                u32 o0 = tx * 64 + h * 32;
                bq.v = *reinterpret_cast<const float4*>(bbase + SWZ(o0));
                bp[0] = bq.u[0]; bp[1] = bq.u[1];
                bq.v = *reinterpret_cast<const float4*>(bbase + SWZ(o0 + 16));
                bp[2] = bq.u[0]; bp[3] = bq.u[1];
#pragma unroll
                for (int i = 0; i < 4; i++)
#pragma unroll
                    for (int j = 0; j < 4; j++)
                        ffma2(acc[i][h * 4 + j], ap[i], bp[j]);
            }
        }
    }

    // ---- epilogue: bias + LIF + store ----
    float4 bq0 = *reinterpret_cast<const float4*>(bias + n0 + tx * 8);
    float4 bq1 = *reinterpret_cast<const float4*>(bias + n0 + tx * 8 + 4);
    const float bv[8] = { bq0.x, bq0.y, bq0.z, bq0.w, bq1.x, bq1.y, bq1.z, bq1.w };

#pragma unroll
    for (int i = 0; i < 4; i++) {
        float lo[8], hi[8];
#pragma unroll
        for (int j = 0; j < 8; j++) unpack2(acc[i][j], lo[j], hi[j]);

        int m_lo = m0 + ty * 8 + 2 * i;
        float* p0 = out + (size_t)m_lo * ND + n0 + tx * 8;
        float* p1 = p0 + ND;

        float4 o;
        o.x = lif16(lo[0] + bv[0]); o.y = lif16(lo[1] + bv[1]);
        o.z = lif16(lo[2] + bv[2]); o.w = lif16(lo[3] + bv[3]);
        *reinterpret_cast<float4*>(p0) = o;
        o.x = lif16(lo[4] + bv[4]); o.y = lif16(lo[5] + bv[5]);
        o.z = lif16(lo[6] + bv[6]); o.w = lif16(lo[7] + bv[7]);
        *reinterpret_cast<float4*>(p0 + 4) = o;
        o.x = lif16(hi[0] + bv[0]); o.y = lif16(hi[1] + bv[1]);
        o.z = lif16(hi[2] + bv[2]); o.w = lif16(hi[3] + bv[3]);
        *reinterpret_cast<float4*>(p1) = o;
        o.x = lif16(hi[4] + bv[4]); o.y = lif16(hi[5] + bv[5]);
        o.z = lif16(hi[6] + bv[6]); o.w = lif16(hi[7] + bv[7]);
        *reinterpret_cast<float4*>(p1 + 4) = o;
    }
}

extern "C" void kernel_launch(void* const* d_in, const int* in_sizes, int n_in,
                              void* d_out, int out_size) {
    const float* x = (const float*)d_in[0];
    const float* W = (const float*)d_in[1];
    const float* b = (const float*)d_in[2];
    float* out = (float*)d_out;

    const int N = in_sizes[2];          // 512
    const int K = in_sizes[1] / N;      // 512
    const int M = in_sizes[0] / K;      // 32768

    dim3 tb(32, 8);
    dim3 tg(K / 32, M / 32);
    transpose_x<<<tg, tb>>>(x, M, K);
    dup_w<<<(N * K + 255) / 256, 256>>>(W, N, K);

    cudaFuncSetAttribute(gemm_lif, cudaFuncAttributeMaxDynamicSharedMemorySize, SM_TOTAL);
    dim3 grid(N / BN, M / BM);
    gemm_lif<<<grid, 256, SM_TOTAL>>>(b, out, M);
}